// round 1
// baseline (speedup 1.0000x reference)
#include <cuda_runtime.h>
#include <cuda_bf16.h>

#define NMAX   100000
#define DDIM   64
#define NGR    64

// Scratch (static device globals; no allocation allowed)
__device__ float g_dis[NMAX];             // deg, then rsqrt(deg) in-place
__device__ float g_t[NMAX * DDIM];        // GEMM output t = f(in) @ W
__device__ float g_agg[NMAX * DDIM];      // aggregation buffer
__device__ float g_pooled[NGR * DDIM];    // global_add_pool result

// ---------------------------------------------------------------------------
// degree / norm precompute
// ---------------------------------------------------------------------------
__global__ void k_init_deg(int n) {
    int i = blockIdx.x * blockDim.x + threadIdx.x;
    if (i < n) g_dis[i] = 1.0f;   // self loop
}

__global__ void k_count_deg(const int* __restrict__ dst, int E) {
    int e = blockIdx.x * blockDim.x + threadIdx.x;
    if (e < E) atomicAdd(&g_dis[dst[e]], 1.0f);
}

__global__ void k_rsqrt_deg(int n) {
    int i = blockIdx.x * blockDim.x + threadIdx.x;
    if (i < n) g_dis[i] = rsqrtf(g_dis[i]);
}

// ---------------------------------------------------------------------------
// GEMM: g_t[n][c] = sum_k f(in[n][k]) * W[k][c]
//   f = relu(. + bprev) when applyPre, else identity
//   in == nullptr means read g_agg (layers 2,3)
// Block: 256 threads, 64 nodes. Each thread: 4 nodes x 4 cols.
// ---------------------------------------------------------------------------
__global__ void __launch_bounds__(256) k_gemm(
    const float* __restrict__ in, const float* __restrict__ W,
    const float* __restrict__ bprev, int applyPre, int n)
{
    __shared__ float xs[64][64];
    __shared__ float ws[64][64];
    const float* src_in = in ? in : g_agg;

    int tid = threadIdx.x;
    int node0 = blockIdx.x * 64;

    #pragma unroll
    for (int idx = tid; idx < 64 * 64; idx += 256)
        ws[idx >> 6][idx & 63] = W[idx];

    for (int idx = tid; idx < 64 * 64; idx += 256) {
        int r = idx >> 6, c = idx & 63;
        int nrow = node0 + r;
        float v = 0.0f;
        if (nrow < n) {
            v = src_in[nrow * 64 + c];
            if (applyPre) v = fmaxf(v + bprev[c], 0.0f);
        }
        xs[r][c] = v;
    }
    __syncthreads();

    int c4 = tid & 15;      // column group: cols [4*c4, 4*c4+3]
    int g  = tid >> 4;      // node group:   nodes [4*g, 4*g+3] within tile
    float acc[4][4];
    #pragma unroll
    for (int j = 0; j < 4; j++)
        #pragma unroll
        for (int q = 0; q < 4; q++) acc[j][q] = 0.0f;

    #pragma unroll
    for (int k = 0; k < 64; k++) {
        float4 w4 = *reinterpret_cast<const float4*>(&ws[k][c4 * 4]);
        #pragma unroll
        for (int j = 0; j < 4; j++) {
            float xv = xs[g * 4 + j][k];
            acc[j][0] += xv * w4.x;
            acc[j][1] += xv * w4.y;
            acc[j][2] += xv * w4.z;
            acc[j][3] += xv * w4.w;
        }
    }

    #pragma unroll
    for (int j = 0; j < 4; j++) {
        int nrow = node0 + g * 4 + j;
        if (nrow < n) {
            float4 o = make_float4(acc[j][0], acc[j][1], acc[j][2], acc[j][3]);
            *reinterpret_cast<float4*>(&g_t[nrow * 64 + c4 * 4]) = o;
        }
    }
}

// ---------------------------------------------------------------------------
// Self-loop init: agg[i][:] = t[i][:] * dis[i]^2   (norm of self loop = 1/deg)
// One thread per float4.
// ---------------------------------------------------------------------------
__global__ void k_selfinit(int n) {
    int idx = blockIdx.x * blockDim.x + threadIdx.x;   // over n*16 float4s
    if (idx < n * 16) {
        int i = idx >> 4;
        float d = g_dis[i];
        float s = d * d;
        float4 v = reinterpret_cast<const float4*>(g_t)[idx];
        v.x *= s; v.y *= s; v.z *= s; v.w *= s;
        reinterpret_cast<float4*>(g_agg)[idx] = v;
    }
}

// ---------------------------------------------------------------------------
// Edge scatter: agg[dst] += t[src] * (dis[src]*dis[dst])
// 16 lanes per edge, each handles one float4, vector red (no return).
// ---------------------------------------------------------------------------
__global__ void k_scatter(const int* __restrict__ src, const int* __restrict__ dst, int E) {
    long long t = (long long)blockIdx.x * blockDim.x + threadIdx.x;
    int e = (int)(t >> 4);
    if (e >= E) return;
    int s = (int)(t & 15);
    int si = src[e];
    int di = dst[e];
    float nm = g_dis[si] * g_dis[di];
    float4 v = reinterpret_cast<const float4*>(g_t)[si * 16 + s];
    float* p = &g_agg[di * 64 + s * 4];
    asm volatile("red.global.add.v4.f32 [%0], {%1,%2,%3,%4};"
                 :: "l"(p), "f"(v.x * nm), "f"(v.y * nm), "f"(v.z * nm), "f"(v.w * nm)
                 : "memory");
}

// ---------------------------------------------------------------------------
// Pool: pooled[batch[i]] += relu(agg[i] + b3)
// batch is sorted -> run-length accumulate per thread, flush on graph change.
// Block: 256 threads = 16 col-float4s x 16 node-chunks; 16 nodes per thread.
// ---------------------------------------------------------------------------
__global__ void k_zero_pooled() {
    int i = blockIdx.x * blockDim.x + threadIdx.x;
    if (i < NGR * DDIM) g_pooled[i] = 0.0f;
}

__device__ __forceinline__ void pool_flush(int gph, int s, float4 sum) {
    float* p = &g_pooled[gph * 64 + s * 4];
    asm volatile("red.global.add.v4.f32 [%0], {%1,%2,%3,%4};"
                 :: "l"(p), "f"(sum.x), "f"(sum.y), "f"(sum.z), "f"(sum.w)
                 : "memory");
}

__global__ void k_pool(const int* __restrict__ batch, const float* __restrict__ b3, int n) {
    int tid = threadIdx.x;
    int s = tid & 15;
    int chunk = tid >> 4;
    int n0 = blockIdx.x * 256 + chunk * 16;
    float4 b4 = reinterpret_cast<const float4*>(b3)[s];

    float4 sum = make_float4(0.f, 0.f, 0.f, 0.f);
    int cur = -1;
    for (int j = 0; j < 16; j++) {
        int nn = n0 + j;
        if (nn >= n) break;
        int gph = batch[nn];
        if (gph != cur) {
            if (cur >= 0) pool_flush(cur, s, sum);
            cur = gph;
            sum = make_float4(0.f, 0.f, 0.f, 0.f);
        }
        float4 v = reinterpret_cast<const float4*>(g_agg)[nn * 16 + s];
        sum.x += fmaxf(v.x + b4.x, 0.0f);
        sum.y += fmaxf(v.y + b4.y, 0.0f);
        sum.z += fmaxf(v.z + b4.z, 0.0f);
        sum.w += fmaxf(v.w + b4.w, 0.0f);
    }
    if (cur >= 0) pool_flush(cur, s, sum);
}

// ---------------------------------------------------------------------------
// Final: out[g] = pooled[g] . lin_w + lin_b
// ---------------------------------------------------------------------------
__global__ void k_final(const float* __restrict__ lw, const float* __restrict__ lb,
                        float* __restrict__ out) {
    int g = threadIdx.x;   // 64 threads
    float s = lb[0];
    #pragma unroll
    for (int c = 0; c < 64; c++)
        s += g_pooled[g * 64 + c] * lw[c];
    out[g] = s;
}

// ---------------------------------------------------------------------------
extern "C" void kernel_launch(void* const* d_in, const int* in_sizes, int n_in,
                              void* d_out, int out_size) {
    const float* x  = (const float*)d_in[0];
    const int*   ei = (const int*)  d_in[1];
    const int*   batch = (const int*)d_in[2];
    const float* W1 = (const float*)d_in[3];
    const float* b1 = (const float*)d_in[4];
    const float* W2 = (const float*)d_in[5];
    const float* b2 = (const float*)d_in[6];
    const float* W3 = (const float*)d_in[7];
    const float* b3 = (const float*)d_in[8];
    const float* lw = (const float*)d_in[9];
    const float* lb = (const float*)d_in[10];
    float* out = (float*)d_out;

    int n = in_sizes[0] / DDIM;
    int E = in_sizes[1] / 2;
    const int* src = ei;
    const int* dst = ei + E;

    // degree + normalization
    k_init_deg<<<(n + 255) / 256, 256>>>(n);
    k_count_deg<<<(E + 255) / 256, 256>>>(dst, E);
    k_rsqrt_deg<<<(n + 255) / 256, 256>>>(n);

    int gemmBlocks = (n + 63) / 64;
    int siBlocks   = (n * 16 + 255) / 256;
    long long st   = (long long)E * 16;
    int scBlocks   = (int)((st + 255) / 256);

    // layer 1
    k_gemm<<<gemmBlocks, 256>>>(x, W1, nullptr, 0, n);
    k_selfinit<<<siBlocks, 256>>>(n);
    k_scatter<<<scBlocks, 256>>>(src, dst, E);
    // layer 2 (bias+relu of layer 1 fused into GEMM input read)
    k_gemm<<<gemmBlocks, 256>>>(nullptr, W2, b1, 1, n);
    k_selfinit<<<siBlocks, 256>>>(n);
    k_scatter<<<scBlocks, 256>>>(src, dst, E);
    // layer 3
    k_gemm<<<gemmBlocks, 256>>>(nullptr, W3, b2, 1, n);
    k_selfinit<<<siBlocks, 256>>>(n);
    k_scatter<<<scBlocks, 256>>>(src, dst, E);

    // pool (bias+relu of layer 3 fused) + final linear
    k_zero_pooled<<<(NGR * DDIM + 255) / 256, 256>>>();
    k_pool<<<(n + 255) / 256, 256>>>(batch, b3, n);
    k_final<<<1, NGR>>>(lw, lb, out);
}

// round 3
// speedup vs baseline: 1.5821x; 1.5821x over previous
#include <cuda_runtime.h>
#include <cuda_bf16.h>

#define NMAX   100000
#define EMAX   1600000
#define DDIM   64
#define NGR    64

// Scratch (static device globals; no allocation allowed)
__device__ float g_dis[NMAX];               // rsqrt(deg)
__device__ float g_t[NMAX * DDIM];          // ts = (f(in) @ W) * dis[row]
__device__ float g_agg[NMAX * DDIM];        // aggregation output
__device__ float g_pooled[NGR * DDIM];
__device__ int   g_hist[NMAX];              // in-degree histogram
__device__ int   g_off[NMAX + 1];           // CSR offsets (by dst)
__device__ int   g_cursor[NMAX];            // fill cursors
__device__ int   g_csr[EMAX];               // CSR src indices
__device__ int   g_bsum[128];               // scan block sums
__device__ int   g_boff[128];               // scanned block sums

// ---------------------------------------------------------------------------
// degree / norm precompute
// ---------------------------------------------------------------------------
__global__ void k_zero_hist(int n) {
    int i = blockIdx.x * blockDim.x + threadIdx.x;
    if (i < n) g_hist[i] = 0;
}

__global__ void k_count(const int* __restrict__ dst, int E) {
    int e = blockIdx.x * blockDim.x + threadIdx.x;
    if (e < E) atomicAdd(&g_hist[dst[e]], 1);
}

__global__ void k_norm(int n) {
    int i = blockIdx.x * blockDim.x + threadIdx.x;
    if (i < n) g_dis[i] = rsqrtf((float)(g_hist[i] + 1));   // +1 self loop
}

// ---------------------------------------------------------------------------
// 2-level exclusive scan of g_hist -> g_off  (1024 items per block)
// ---------------------------------------------------------------------------
__global__ void __launch_bounds__(1024) k_scan1(int n) {
    __shared__ int sh[32];
    int i = blockIdx.x * 1024 + threadIdx.x;
    int lane = threadIdx.x & 31, w = threadIdx.x >> 5;
    int v = (i < n) ? g_hist[i] : 0;
    int x = v;
    #pragma unroll
    for (int o = 1; o < 32; o <<= 1) {
        int y = __shfl_up_sync(~0u, x, o);
        if (lane >= o) x += y;
    }
    if (lane == 31) sh[w] = x;
    __syncthreads();
    if (threadIdx.x < 32) {
        int y = sh[threadIdx.x];
        #pragma unroll
        for (int o = 1; o < 32; o <<= 1) {
            int z = __shfl_up_sync(~0u, y, o);
            if (threadIdx.x >= o) y += z;
        }
        sh[threadIdx.x] = y;
    }
    __syncthreads();
    int base = (w > 0) ? sh[w - 1] : 0;
    int incl = x + base;
    if (i < n) g_off[i] = incl - v;          // exclusive within block
    if (threadIdx.x == 1023) g_bsum[blockIdx.x] = incl;
}

__global__ void k_scan2(int nb) {
    // single block, 128 threads; nb <= 128
    __shared__ int sh[4];
    int t = threadIdx.x, lane = t & 31, w = t >> 5;
    int v = (t < nb) ? g_bsum[t] : 0;
    int x = v;
    #pragma unroll
    for (int o = 1; o < 32; o <<= 1) {
        int y = __shfl_up_sync(~0u, x, o);
        if (lane >= o) x += y;
    }
    if (lane == 31) sh[w] = x;
    __syncthreads();
    if (t < 4) {
        int y = sh[t];
        #pragma unroll
        for (int o = 1; o < 4; o <<= 1) {
            int z = __shfl_up_sync(0xF, y, o);
            if (t >= o) y += z;
        }
        sh[t] = y;
    }
    __syncthreads();
    int base = (w > 0) ? sh[w - 1] : 0;
    if (t < nb) g_boff[t] = x + base - v;    // exclusive
}

__global__ void k_scan3(int n, int E) {
    int i = blockIdx.x * blockDim.x + threadIdx.x;
    if (i < n) {
        int o = g_off[i] + g_boff[i >> 10];
        g_off[i] = o;
        g_cursor[i] = o;
    }
    if (i == 0) g_off[n] = E;
}

__global__ void k_fill(const int* __restrict__ src, const int* __restrict__ dst, int E) {
    int e = blockIdx.x * blockDim.x + threadIdx.x;
    if (e < E) {
        int pos = atomicAdd(&g_cursor[dst[e]], 1);
        g_csr[pos] = src[e];
    }
}

// ---------------------------------------------------------------------------
// GEMM: g_t[n][c] = dis[n] * sum_k f(in[n][k]) * W[k][c]
//   f = relu(. + bprev) when applyPre, else identity
//   in == nullptr means read g_agg (layers 2,3)
// Block: 256 threads, 64 nodes. Each thread: 4 nodes x 4 cols.
// xs stored transposed (padded) so inner loop is 2x LDS.128 + 16 FMA.
// ---------------------------------------------------------------------------
__global__ void __launch_bounds__(256) k_gemm(
    const float* __restrict__ in, const float* __restrict__ W,
    const float* __restrict__ bprev, int applyPre, int n)
{
    __shared__ float xs[64][68];   // [k][node], pad 68 keeps 16B alignment
    __shared__ float ws[64][64];   // [k][col]
    const float* src_in = in ? in : g_agg;

    int tid = threadIdx.x;
    int node0 = blockIdx.x * 64;

    #pragma unroll
    for (int idx = tid; idx < 64 * 64; idx += 256)
        ws[idx >> 6][idx & 63] = W[idx];

    for (int idx = tid; idx < 64 * 64; idx += 256) {
        int r = idx >> 6, c = idx & 63;        // r = node-in-tile, c = k
        int nrow = node0 + r;
        float v = 0.0f;
        if (nrow < n) {
            v = src_in[nrow * 64 + c];
            if (applyPre) v = fmaxf(v + bprev[c], 0.0f);
        }
        xs[c][r] = v;                           // transposed store
    }
    __syncthreads();

    int c4 = tid & 15;      // column group: cols [4*c4, 4*c4+3]
    int g  = tid >> 4;      // node group:   nodes [4*g, 4*g+3] within tile
    float4 acc[4];
    #pragma unroll
    for (int j = 0; j < 4; j++) acc[j] = make_float4(0.f, 0.f, 0.f, 0.f);

    #pragma unroll
    for (int k = 0; k < 64; k++) {
        float4 w4 = *reinterpret_cast<const float4*>(&ws[k][c4 * 4]);
        float4 x4 = *reinterpret_cast<const float4*>(&xs[k][g * 4]);
        acc[0].x += x4.x * w4.x; acc[0].y += x4.x * w4.y; acc[0].z += x4.x * w4.z; acc[0].w += x4.x * w4.w;
        acc[1].x += x4.y * w4.x; acc[1].y += x4.y * w4.y; acc[1].z += x4.y * w4.z; acc[1].w += x4.y * w4.w;
        acc[2].x += x4.z * w4.x; acc[2].y += x4.z * w4.y; acc[2].z += x4.z * w4.z; acc[2].w += x4.z * w4.w;
        acc[3].x += x4.w * w4.x; acc[3].y += x4.w * w4.y; acc[3].z += x4.w * w4.z; acc[3].w += x4.w * w4.w;
    }

    #pragma unroll
    for (int j = 0; j < 4; j++) {
        int nrow = node0 + g * 4 + j;
        if (nrow < n) {
            float d = g_dis[nrow];
            float4 o = acc[j];
            o.x *= d; o.y *= d; o.z *= d; o.w *= d;
            *reinterpret_cast<float4*>(&g_t[nrow * 64 + c4 * 4]) = o;
        }
    }
}

// ---------------------------------------------------------------------------
// Aggregation (gather, no atomics):
//   agg[i] = dis[i] * ( ts[i] + sum_{j in CSR[i]} ts[j] )
// 16 lanes per node (one float4 slice each). 2 nodes per warp, 16 per block.
// ---------------------------------------------------------------------------
__global__ void __launch_bounds__(256) k_agg(int n) {
    int tid = threadIdx.x;
    int lane = tid & 31;
    int warp = tid >> 5;
    int node = blockIdx.x * 16 + warp * 2 + (lane >> 4);
    int s = lane & 15;
    if (node >= n) return;

    const float4* __restrict__ ts4 = reinterpret_cast<const float4*>(g_t);
    int beg = g_off[node];
    int end = g_off[node + 1];

    float4 acc = ts4[node * 16 + s];   // self loop (ts already has dis[self])
    int j = beg;
    for (; j + 4 <= end; j += 4) {
        int s0 = g_csr[j], s1 = g_csr[j + 1], s2 = g_csr[j + 2], s3 = g_csr[j + 3];
        float4 v0 = ts4[s0 * 16 + s];
        float4 v1 = ts4[s1 * 16 + s];
        float4 v2 = ts4[s2 * 16 + s];
        float4 v3 = ts4[s3 * 16 + s];
        acc.x += (v0.x + v1.x) + (v2.x + v3.x);
        acc.y += (v0.y + v1.y) + (v2.y + v3.y);
        acc.z += (v0.z + v1.z) + (v2.z + v3.z);
        acc.w += (v0.w + v1.w) + (v2.w + v3.w);
    }
    for (; j < end; j++) {
        float4 v = ts4[g_csr[j] * 16 + s];
        acc.x += v.x; acc.y += v.y; acc.z += v.z; acc.w += v.w;
    }
    float d = g_dis[node];
    acc.x *= d; acc.y *= d; acc.z *= d; acc.w *= d;
    reinterpret_cast<float4*>(g_agg)[node * 16 + s] = acc;
}

// ---------------------------------------------------------------------------
// Pool: pooled[batch[i]] += relu(agg[i] + b3); batch sorted -> run-length.
// ---------------------------------------------------------------------------
__global__ void k_zero_pooled() {
    int i = blockIdx.x * blockDim.x + threadIdx.x;
    if (i < NGR * DDIM) g_pooled[i] = 0.0f;
}

__device__ __forceinline__ void pool_flush(int gph, int s, float4 sum) {
    float* p = &g_pooled[gph * 64 + s * 4];
    asm volatile("red.global.add.v4.f32 [%0], {%1,%2,%3,%4};"
                 :: "l"(p), "f"(sum.x), "f"(sum.y), "f"(sum.z), "f"(sum.w)
                 : "memory");
}

__global__ void k_pool(const int* __restrict__ batch, const float* __restrict__ b3, int n) {
    int tid = threadIdx.x;
    int s = tid & 15;
    int chunk = tid >> 4;
    int n0 = blockIdx.x * 256 + chunk * 16;
    float4 b4 = reinterpret_cast<const float4*>(b3)[s];

    float4 sum = make_float4(0.f, 0.f, 0.f, 0.f);
    int cur = -1;
    for (int j = 0; j < 16; j++) {
        int nn = n0 + j;
        if (nn >= n) break;
        int gph = batch[nn];
        if (gph != cur) {
            if (cur >= 0) pool_flush(cur, s, sum);
            cur = gph;
            sum = make_float4(0.f, 0.f, 0.f, 0.f);
        }
        float4 v = reinterpret_cast<const float4*>(g_agg)[nn * 16 + s];
        sum.x += fmaxf(v.x + b4.x, 0.0f);
        sum.y += fmaxf(v.y + b4.y, 0.0f);
        sum.z += fmaxf(v.z + b4.z, 0.0f);
        sum.w += fmaxf(v.w + b4.w, 0.0f);
    }
    if (cur >= 0) pool_flush(cur, s, sum);
}

__global__ void k_final(const float* __restrict__ lw, const float* __restrict__ lb,
                        float* __restrict__ out) {
    int g = threadIdx.x;   // 64 threads
    float s = lb[0];
    #pragma unroll
    for (int c = 0; c < 64; c++)
        s += g_pooled[g * 64 + c] * lw[c];
    out[g] = s;
}

// ---------------------------------------------------------------------------
extern "C" void kernel_launch(void* const* d_in, const int* in_sizes, int n_in,
                              void* d_out, int out_size) {
    const float* x  = (const float*)d_in[0];
    const int*   ei = (const int*)  d_in[1];
    const int*   batch = (const int*)d_in[2];
    const float* W1 = (const float*)d_in[3];
    const float* b1 = (const float*)d_in[4];
    const float* W2 = (const float*)d_in[5];
    const float* b2 = (const float*)d_in[6];
    const float* W3 = (const float*)d_in[7];
    const float* b3 = (const float*)d_in[8];
    const float* lw = (const float*)d_in[9];
    const float* lb = (const float*)d_in[10];
    float* out = (float*)d_out;

    int n = in_sizes[0] / DDIM;
    int E = in_sizes[1] / 2;
    const int* src = ei;
    const int* dst = ei + E;

    // degree + normalization + CSR build
    k_zero_hist<<<(n + 255) / 256, 256>>>(n);
    k_count<<<(E + 255) / 256, 256>>>(dst, E);
    k_norm<<<(n + 255) / 256, 256>>>(n);
    int nb = (n + 1023) / 1024;
    k_scan1<<<nb, 1024>>>(n);
    k_scan2<<<1, 128>>>(nb);
    k_scan3<<<(n + 255) / 256, 256>>>(n, E);
    k_fill<<<(E + 255) / 256, 256>>>(src, dst, E);

    int gemmBlocks = (n + 63) / 64;
    int aggBlocks  = (n + 15) / 16;

    // layer 1
    k_gemm<<<gemmBlocks, 256>>>(x, W1, nullptr, 0, n);
    k_agg<<<aggBlocks, 256>>>(n);
    // layer 2 (bias+relu of layer 1 fused into GEMM input read)
    k_gemm<<<gemmBlocks, 256>>>(nullptr, W2, b1, 1, n);
    k_agg<<<aggBlocks, 256>>>(n);
    // layer 3
    k_gemm<<<gemmBlocks, 256>>>(nullptr, W3, b2, 1, n);
    k_agg<<<aggBlocks, 256>>>(n);

    // pool (bias+relu of layer 3 fused) + final linear
    k_zero_pooled<<<(NGR * DDIM + 255) / 256, 256>>>();   // FIX: all 4096 elems
    k_pool<<<(n + 255) / 256, 256>>>(batch, b3, n);
    k_final<<<1, NGR>>>(lw, lb, out);
}

// round 6
// speedup vs baseline: 2.0156x; 1.2740x over previous
#include <cuda_runtime.h>
#include <cuda_fp16.h>

#define NMAX   100000
#define EMAX   1600000
#define DDIM   64
#define NGR    64

// Scratch (static device globals; no allocation allowed)
__device__ float g_dis[NMAX];               // rsqrt(deg)
__device__ uint4 g_th[NMAX * 8];            // ts in fp16: 64 halves = 8 uint4 per node
__device__ float g_agg[NMAX * DDIM];        // aggregation output (fp32)
__device__ float g_pooled[NGR * DDIM];
__device__ int   g_hist[NMAX];              // in-degree histogram
__device__ int   g_off[NMAX + 1];           // CSR offsets (by dst)
__device__ int   g_cursor[NMAX];            // fill cursors
__device__ int   g_csr[EMAX];               // CSR src indices
__device__ int   g_bsum[128];               // scan block sums
__device__ int   g_boff[128];               // scanned block sums

// ---------------------------------------------------------------------------
// degree precompute
// ---------------------------------------------------------------------------
__global__ void k_zero_hist(int n) {
    int i = blockIdx.x * blockDim.x + threadIdx.x;
    if (i < n) g_hist[i] = 0;
}

__global__ void k_count(const int* __restrict__ dst, int E) {
    int e = blockIdx.x * blockDim.x + threadIdx.x;
    if (e < E) atomicAdd(&g_hist[dst[e]], 1);
}

// ---------------------------------------------------------------------------
// 2-level exclusive scan of g_hist -> g_off; also writes g_dis = rsqrt(deg+1)
// ---------------------------------------------------------------------------
__global__ void __launch_bounds__(1024) k_scan1(int n) {
    __shared__ int sh[32];
    int i = blockIdx.x * 1024 + threadIdx.x;
    int lane = threadIdx.x & 31, w = threadIdx.x >> 5;
    int v = (i < n) ? g_hist[i] : 0;
    if (i < n) g_dis[i] = rsqrtf((float)(v + 1));   // fused norm
    int x = v;
    #pragma unroll
    for (int o = 1; o < 32; o <<= 1) {
        int y = __shfl_up_sync(~0u, x, o);
        if (lane >= o) x += y;
    }
    if (lane == 31) sh[w] = x;
    __syncthreads();
    if (threadIdx.x < 32) {
        int y = sh[threadIdx.x];
        #pragma unroll
        for (int o = 1; o < 32; o <<= 1) {
            int z = __shfl_up_sync(~0u, y, o);
            if (threadIdx.x >= o) y += z;
        }
        sh[threadIdx.x] = y;
    }
    __syncthreads();
    int base = (w > 0) ? sh[w - 1] : 0;
    int incl = x + base;
    if (i < n) g_off[i] = incl - v;          // exclusive within block
    if (threadIdx.x == 1023) g_bsum[blockIdx.x] = incl;
}

__global__ void k_scan2(int nb) {
    __shared__ int sh[4];
    int t = threadIdx.x, lane = t & 31, w = t >> 5;
    int v = (t < nb) ? g_bsum[t] : 0;
    int x = v;
    #pragma unroll
    for (int o = 1; o < 32; o <<= 1) {
        int y = __shfl_up_sync(~0u, x, o);
        if (lane >= o) x += y;
    }
    if (lane == 31) sh[w] = x;
    __syncthreads();
    if (t < 4) {
        int y = sh[t];
        #pragma unroll
        for (int o = 1; o < 4; o <<= 1) {
            int z = __shfl_up_sync(0xF, y, o);
            if (t >= o) y += z;
        }
        sh[t] = y;
    }
    __syncthreads();
    int base = (w > 0) ? sh[w - 1] : 0;
    if (t < nb) g_boff[t] = x + base - v;    // exclusive
}

__global__ void k_scan3(int n, int E) {
    int i = blockIdx.x * blockDim.x + threadIdx.x;
    if (i < n) {
        int o = g_off[i] + g_boff[i >> 10];
        g_off[i] = o;
        g_cursor[i] = o;
    }
    if (i == 0) g_off[n] = E;
}

__global__ void k_fill(const int* __restrict__ src, const int* __restrict__ dst, int E) {
    int e = blockIdx.x * blockDim.x + threadIdx.x;
    if (e < E) {
        int pos = atomicAdd(&g_cursor[dst[e]], 1);
        g_csr[pos] = src[e];
    }
}

// ---------------------------------------------------------------------------
// GEMM: ts[n][c] = fp16( dis[n] * sum_k f(in[n][k]) * W[k][c] )
//   f = relu(. + bprev) when applyPre, else identity
//   in == nullptr means read g_agg (layers 2,3)
// Block: 256 threads, 128 nodes. Each thread: 8 nodes x 4 cols.
// ---------------------------------------------------------------------------
__global__ void __launch_bounds__(256) k_gemm(
    const float* __restrict__ in, const float* __restrict__ W,
    const float* __restrict__ bprev, int applyPre, int n)
{
    __shared__ float xs[128][68];  // [node][k], pad 68 -> conflict-free stores
    __shared__ float ws[64][64];   // [k][col]
    const float* src_in = in ? in : g_agg;

    int tid = threadIdx.x;
    int node0 = blockIdx.x * 128;

    #pragma unroll
    for (int idx = tid; idx < 64 * 64; idx += 256)
        ws[idx >> 6][idx & 63] = W[idx];

    for (int idx = tid; idx < 128 * 64; idx += 256) {
        int r = idx >> 6, c = idx & 63;
        int nrow = node0 + r;
        float v = 0.0f;
        if (nrow < n) {
            v = src_in[nrow * 64 + c];
            if (applyPre) v = fmaxf(v + bprev[c], 0.0f);
        }
        xs[r][c] = v;
    }
    __syncthreads();

    int c4 = tid & 15;      // column group: cols [4*c4, 4*c4+3]
    int g  = tid >> 4;      // node group:   nodes [8*g, 8*g+7] within tile
    float4 acc[8];
    #pragma unroll
    for (int j = 0; j < 8; j++) acc[j] = make_float4(0.f, 0.f, 0.f, 0.f);

    #pragma unroll 4
    for (int k = 0; k < 64; k++) {
        float4 w4 = *reinterpret_cast<const float4*>(&ws[k][c4 * 4]);
        #pragma unroll
        for (int j = 0; j < 8; j++) {
            float xv = xs[g * 8 + j][k];
            acc[j].x += xv * w4.x;
            acc[j].y += xv * w4.y;
            acc[j].z += xv * w4.z;
            acc[j].w += xv * w4.w;
        }
    }

    #pragma unroll
    for (int j = 0; j < 8; j++) {
        int nrow = node0 + g * 8 + j;
        if (nrow < n) {
            float d = g_dis[nrow];
            __half2 h0 = __floats2half2_rn(acc[j].x * d, acc[j].y * d);
            __half2 h1 = __floats2half2_rn(acc[j].z * d, acc[j].w * d);
            uint2 u;
            u.x = *reinterpret_cast<unsigned*>(&h0);
            u.y = *reinterpret_cast<unsigned*>(&h1);
            reinterpret_cast<uint2*>(g_th)[nrow * 16 + c4] = u;
        }
    }
}

// ---------------------------------------------------------------------------
// Aggregation (gather, no atomics, fp16 messages, fp32 accumulate):
//   agg[i] = dis[i] * ( ts[i] + sum_{j in CSR[i]} ts[j] )
// 8 lanes per node (one uint4 = 8 halves each). 4 nodes/warp, 32/block.
// ---------------------------------------------------------------------------
__device__ __forceinline__ void addh8(float* acc, uint4 v) {
    const __half2* h = reinterpret_cast<const __half2*>(&v);
    float2 f0 = __half22float2(h[0]);
    float2 f1 = __half22float2(h[1]);
    float2 f2 = __half22float2(h[2]);
    float2 f3 = __half22float2(h[3]);
    acc[0] += f0.x; acc[1] += f0.y;
    acc[2] += f1.x; acc[3] += f1.y;
    acc[4] += f2.x; acc[5] += f2.y;
    acc[6] += f3.x; acc[7] += f3.y;
}

__global__ void __launch_bounds__(256) k_agg(int n) {
    int tid = threadIdx.x;
    int lane = tid & 31;
    int warp = tid >> 5;
    int node = blockIdx.x * 32 + warp * 4 + (lane >> 3);
    int s = lane & 7;
    if (node >= n) return;

    float acc[8];
    #pragma unroll
    for (int q = 0; q < 8; q++) acc[q] = 0.0f;

    addh8(acc, g_th[node * 8 + s]);     // self loop (ts already has dis[self])

    int beg = g_off[node];
    int end = g_off[node + 1];
    int j = beg;
    for (; j + 4 <= end; j += 4) {
        int s0 = g_csr[j], s1 = g_csr[j + 1], s2 = g_csr[j + 2], s3 = g_csr[j + 3];
        uint4 v0 = g_th[s0 * 8 + s];
        uint4 v1 = g_th[s1 * 8 + s];
        uint4 v2 = g_th[s2 * 8 + s];
        uint4 v3 = g_th[s3 * 8 + s];
        addh8(acc, v0); addh8(acc, v1); addh8(acc, v2); addh8(acc, v3);
    }
    for (; j < end; j++)
        addh8(acc, g_th[g_csr[j] * 8 + s]);

    float d = g_dis[node];
    float4 o0 = make_float4(acc[0] * d, acc[1] * d, acc[2] * d, acc[3] * d);
    float4 o1 = make_float4(acc[4] * d, acc[5] * d, acc[6] * d, acc[7] * d);
    float4* out = reinterpret_cast<float4*>(&g_agg[node * 64 + s * 8]);
    out[0] = o0;
    out[1] = o1;
}

// ---------------------------------------------------------------------------
// Pool: pooled[batch[i]] += relu(agg[i] + b3); batch sorted -> run-length.
// ---------------------------------------------------------------------------
__global__ void k_zero_pooled() {
    int i = blockIdx.x * blockDim.x + threadIdx.x;
    if (i < NGR * DDIM) g_pooled[i] = 0.0f;
}

__device__ __forceinline__ void pool_flush(int gph, int s, float4 sum) {
    float* p = &g_pooled[gph * 64 + s * 4];
    asm volatile("red.global.add.v4.f32 [%0], {%1,%2,%3,%4};"
                 :: "l"(p), "f"(sum.x), "f"(sum.y), "f"(sum.z), "f"(sum.w)
                 : "memory");
}

__global__ void k_pool(const int* __restrict__ batch, const float* __restrict__ b3, int n) {
    int tid = threadIdx.x;
    int s = tid & 15;
    int chunk = tid >> 4;
    int n0 = blockIdx.x * 256 + chunk * 16;
    float4 b4 = reinterpret_cast<const float4*>(b3)[s];

    float4 sum = make_float4(0.f, 0.f, 0.f, 0.f);
    int cur = -1;
    for (int j = 0; j < 16; j++) {
        int nn = n0 + j;
        if (nn >= n) break;
        int gph = batch[nn];
        if (gph != cur) {
            if (cur >= 0) pool_flush(cur, s, sum);
            cur = gph;
            sum = make_float4(0.f, 0.f, 0.f, 0.f);
        }
        float4 v = reinterpret_cast<const float4*>(g_agg)[nn * 16 + s];
        sum.x += fmaxf(v.x + b4.x, 0.0f);
        sum.y += fmaxf(v.y + b4.y, 0.0f);
        sum.z += fmaxf(v.z + b4.z, 0.0f);
        sum.w += fmaxf(v.w + b4.w, 0.0f);
    }
    if (cur >= 0) pool_flush(cur, s, sum);
}

__global__ void k_final(const float* __restrict__ lw, const float* __restrict__ lb,
                        float* __restrict__ out) {
    int g = threadIdx.x;   // 64 threads
    float s = lb[0];
    #pragma unroll
    for (int c = 0; c < 64; c++)
        s += g_pooled[g * 64 + c] * lw[c];
    out[g] = s;
}

// ---------------------------------------------------------------------------
extern "C" void kernel_launch(void* const* d_in, const int* in_sizes, int n_in,
                              void* d_out, int out_size) {
    const float* x  = (const float*)d_in[0];
    const int*   ei = (const int*)  d_in[1];
    const int*   batch = (const int*)d_in[2];
    const float* W1 = (const float*)d_in[3];
    const float* b1 = (const float*)d_in[4];
    const float* W2 = (const float*)d_in[5];
    const float* b2 = (const float*)d_in[6];
    const float* W3 = (const float*)d_in[7];
    const float* b3 = (const float*)d_in[8];
    const float* lw = (const float*)d_in[9];
    const float* lb = (const float*)d_in[10];
    float* out = (float*)d_out;

    int n = in_sizes[0] / DDIM;
    int E = in_sizes[1] / 2;
    const int* src = ei;
    const int* dst = ei + E;

    // degree + normalization + CSR build
    k_zero_hist<<<(n + 255) / 256, 256>>>(n);
    k_count<<<(E + 255) / 256, 256>>>(dst, E);
    int nb = (n + 1023) / 1024;
    k_scan1<<<nb, 1024>>>(n);
    k_scan2<<<1, 128>>>(nb);
    k_scan3<<<(n + 255) / 256, 256>>>(n, E);
    k_fill<<<(E + 255) / 256, 256>>>(src, dst, E);

    int gemmBlocks = (n + 127) / 128;
    int aggBlocks  = (n + 31) / 32;

    // layer 1
    k_gemm<<<gemmBlocks, 256>>>(x, W1, nullptr, 0, n);
    k_agg<<<aggBlocks, 256>>>(n);
    // layer 2 (bias+relu of layer 1 fused into GEMM input read)
    k_gemm<<<gemmBlocks, 256>>>(nullptr, W2, b1, 1, n);
    k_agg<<<aggBlocks, 256>>>(n);
    // layer 3
    k_gemm<<<gemmBlocks, 256>>>(nullptr, W3, b2, 1, n);
    k_agg<<<aggBlocks, 256>>>(n);

    // pool (bias+relu of layer 3 fused) + final linear
    k_zero_pooled<<<(NGR * DDIM + 255) / 256, 256>>>();
    k_pool<<<(n + 255) / 256, 256>>>(batch, b3, n);
    k_final<<<1, NGR>>>(lw, lb, out);
}